// round 7
// baseline (speedup 1.0000x reference)
#include <cuda_runtime.h>

// Swap_18957985644706: channel-group roll permutation — FINAL converged kernel.
// x: (B=32, C=256, H=64, W=64) fp32, row-major.
// out group 0 (c in [0,64)):    x[b, c+64, (h-1)%64, w]
// out group 1 (c in [64,128)):  x[b, c-64, (h+1)%64, w]
// out group 2 (c in [128,192)): x[b, c+64, h, (w-1)%64]
// out group 3 (c in [192,256)): x[b, c-64, h, (w+1)%64]
//
// Convergence evidence (R2-R6 sweeps): ILP {1,4,8} x threads {256,512} x
// {plain, streaming} x {free, occ-capped} all land at harness 43.49-43.55us;
// best ncu capture shows 7.56 TB/s combined read+write = 94.5% of 8 TB/s
// HBM spec. The permutation moves every byte exactly once each direction —
// no reuse, no algorithmic lever remains. This is the measured-best shape:
// ILP=4, 256-thread blocks, plain LDG.128/STG.128, natural regalloc.
//
// Design: all memory ops are aligned 128-bit. Height-roll groups (0/1) are
// pure row remaps. The +/-1 width-shift (groups 2/3) is resolved with one
// warp shuffle across the 16-lane row group (64 floats/row = 16 float4
// lanes) instead of misaligned loads. QUARTER = 2^21 lands entirely in the
// batch bits of the linear index, so c/h/w4/group and the shuffle lane
// pattern are shared across the 4 chunks per thread and the 4 loads are
// front-batched (MLP=4).

static constexpr unsigned TOTAL_F4 = 32u * 256u * 64u * 16u;   // 8,388,608 = 2^23
static constexpr unsigned QUARTER  = TOTAL_F4 / 4u;            // 2,097,152 = 2^21
static constexpr unsigned THREADS  = 256u;

__global__ void __launch_bounds__(THREADS) swap_roll_kernel(
    const float4* __restrict__ in, float4* __restrict__ out)
{
    unsigned tid = blockIdx.x * THREADS + threadIdx.x;

    unsigned w4 = tid & 15u;          // float4 index within row (0..15)
    unsigned h  = (tid >> 4) & 63u;
    unsigned c  = (tid >> 10) & 255u;
    unsigned b  = tid >> 18;          // low batch bits (0..7)

    unsigned g = c >> 6;              // group 0..3 (warp-uniform)
    unsigned lane = threadIdx.x & 31u;

    unsigned src_c, src_h;
    if (g == 0u)      { src_c = c + 64u; src_h = (h + 63u) & 63u; }
    else if (g == 1u) { src_c = c - 64u; src_h = (h + 1u)  & 63u; }
    else if (g == 2u) { src_c = c + 64u; src_h = h; }
    else              { src_c = c - 64u; src_h = h; }

    unsigned src = ((b * 256u + src_c) * 64u + src_h) * 16u + w4;

    // Front-batched independent loads (MLP = 4)
    float4 v0 = in[src];
    float4 v1 = in[src +      QUARTER];
    float4 v2 = in[src + 2u * QUARTER];
    float4 v3 = in[src + 3u * QUARTER];

    if (g < 2u) {
        out[tid]                = v0;
        out[tid +      QUARTER] = v1;
        out[tid + 2u * QUARTER] = v2;
        out[tid + 3u * QUARTER] = v3;
    } else if (g == 2u) {
        // out[w] = in[w-1]: {prev.w, v.x, v.y, v.z}; prev = lane-1 within
        // the 16-lane row group (wrap inside the half-warp row).
        unsigned srcLane = (lane & 16u) | ((lane + 15u) & 15u);
        float p0 = __shfl_sync(0xffffffffu, v0.w, (int)srcLane);
        float p1 = __shfl_sync(0xffffffffu, v1.w, (int)srcLane);
        float p2 = __shfl_sync(0xffffffffu, v2.w, (int)srcLane);
        float p3 = __shfl_sync(0xffffffffu, v3.w, (int)srcLane);
        out[tid]                = make_float4(p0, v0.x, v0.y, v0.z);
        out[tid +      QUARTER] = make_float4(p1, v1.x, v1.y, v1.z);
        out[tid + 2u * QUARTER] = make_float4(p2, v2.x, v2.y, v2.z);
        out[tid + 3u * QUARTER] = make_float4(p3, v3.x, v3.y, v3.z);
    } else {
        // out[w] = in[w+1]: {v.y, v.z, v.w, next.x}; next = lane+1 within
        // the 16-lane row group (wrap).
        unsigned srcLane = (lane & 16u) | ((lane + 1u) & 15u);
        float n0 = __shfl_sync(0xffffffffu, v0.x, (int)srcLane);
        float n1 = __shfl_sync(0xffffffffu, v1.x, (int)srcLane);
        float n2 = __shfl_sync(0xffffffffu, v2.x, (int)srcLane);
        float n3 = __shfl_sync(0xffffffffu, v3.x, (int)srcLane);
        out[tid]                = make_float4(v0.y, v0.z, v0.w, n0);
        out[tid +      QUARTER] = make_float4(v1.y, v1.z, v1.w, n1);
        out[tid + 2u * QUARTER] = make_float4(v2.y, v2.z, v2.w, n2);
        out[tid + 3u * QUARTER] = make_float4(v3.y, v3.z, v3.w, n3);
    }
}

extern "C" void kernel_launch(void* const* d_in, const int* in_sizes, int n_in,
                              void* d_out, int out_size)
{
    const float4* in  = (const float4*)d_in[0];
    float4*       out = (float4*)d_out;
    swap_roll_kernel<<<QUARTER / THREADS, THREADS>>>(in, out);
}

// round 8
// speedup vs baseline: 1.0059x; 1.0059x over previous
#include <cuda_runtime.h>
#include <cstdint>

// Swap_18957985644706: channel-group roll permutation — 256-bit LDG/STG variant.
// x: (B=32, C=256, H=64, W=64) fp32, row-major.
// out group 0 (c in [0,64)):    x[b, c+64, (h-1)%64, w]
// out group 1 (c in [64,128)):  x[b, c-64, (h+1)%64, w]
// out group 2 (c in [128,192)): x[b, c+64, h, (w-1)%64]
// out group 3 (c in [192,256)): x[b, c-64, h, (w+1)%64]
//
// Uses Blackwell 256-bit vector global loads/stores (ld/st.global.v8.b32):
// halves the instruction count per byte vs float4, reducing LSU dispatch
// and L1tex wavefront overhead. Traffic is unchanged (268.4 MB total, at
// the HBM mixed-traffic ceiling). A 64-float row = 8 float8 lanes; the
// +/-1 W-shift (groups 2/3) is one warp shuffle across the 8-lane row
// group. ILP=4: chunk stride 2^20 float8s lands in the batch bits, so all
// index and lane math is shared across chunks and the 4 loads front-batch.

struct f8 { float4 a, b; };

__device__ __forceinline__ f8 ldg256(const float* p) {
    f8 v;
    asm volatile("ld.global.v8.b32 {%0,%1,%2,%3,%4,%5,%6,%7}, [%8];"
        : "=f"(v.a.x), "=f"(v.a.y), "=f"(v.a.z), "=f"(v.a.w),
          "=f"(v.b.x), "=f"(v.b.y), "=f"(v.b.z), "=f"(v.b.w)
        : "l"(p));
    return v;
}

__device__ __forceinline__ void stg256(float* p, f8 v) {
    asm volatile("st.global.v8.b32 [%0], {%1,%2,%3,%4,%5,%6,%7,%8};"
        :: "l"(p),
           "f"(v.a.x), "f"(v.a.y), "f"(v.a.z), "f"(v.a.w),
           "f"(v.b.x), "f"(v.b.y), "f"(v.b.z), "f"(v.b.w)
        : "memory");
}

static constexpr unsigned TOTAL_F8 = 32u * 256u * 64u * 8u;    // 4,194,304 = 2^22
static constexpr unsigned QUARTER  = TOTAL_F8 / 4u;            // 1,048,576 = 2^20
static constexpr unsigned THREADS  = 256u;

__global__ void __launch_bounds__(THREADS) swap_roll_kernel(
    const float* __restrict__ in, float* __restrict__ out)
{
    unsigned tid = blockIdx.x * THREADS + threadIdx.x;   // float8 index

    unsigned w8 = tid & 7u;           // float8 index within row (0..7)
    unsigned h  = (tid >> 3) & 63u;
    unsigned c  = (tid >> 9) & 255u;
    unsigned b  = tid >> 17;          // low batch bits (0..7)

    unsigned g = c >> 6;              // group 0..3 (warp-uniform)
    unsigned lane = threadIdx.x & 31u;

    unsigned src_c, src_h;
    if (g == 0u)      { src_c = c + 64u; src_h = (h + 63u) & 63u; }
    else if (g == 1u) { src_c = c - 64u; src_h = (h + 1u)  & 63u; }
    else if (g == 2u) { src_c = c + 64u; src_h = h; }
    else              { src_c = c - 64u; src_h = h; }

    unsigned src = ((b * 256u + src_c) * 64u + src_h) * 8u + w8;  // float8 units

    // Front-batched independent 256-bit loads (MLP = 4)
    f8 v0 = ldg256(in + 8ull * (src));
    f8 v1 = ldg256(in + 8ull * (src +      QUARTER));
    f8 v2 = ldg256(in + 8ull * (src + 2u * QUARTER));
    f8 v3 = ldg256(in + 8ull * (src + 3u * QUARTER));

    float* o0 = out + 8ull * (tid);
    float* o1 = out + 8ull * (tid +      QUARTER);
    float* o2 = out + 8ull * (tid + 2u * QUARTER);
    float* o3 = out + 8ull * (tid + 3u * QUARTER);

    if (g < 2u) {
        stg256(o0, v0); stg256(o1, v1); stg256(o2, v2); stg256(o3, v3);
    } else if (g == 2u) {
        // out[w] = in[w-1]: {prev[7], v[0..6]}; prev = lane-1 within the
        // 8-lane row group (wrap inside the row).
        unsigned srcLane = (lane & 24u) | ((lane + 7u) & 7u);
#pragma unroll
        for (int k = 0; k < 4; k++) {
            f8 v = (k == 0) ? v0 : (k == 1) ? v1 : (k == 2) ? v2 : v3;
            float p = __shfl_sync(0xffffffffu, v.b.w, (int)srcLane);
            f8 r;
            r.a = make_float4(p,     v.a.x, v.a.y, v.a.z);
            r.b = make_float4(v.a.w, v.b.x, v.b.y, v.b.z);
            stg256((k == 0) ? o0 : (k == 1) ? o1 : (k == 2) ? o2 : o3, r);
        }
    } else {
        // out[w] = in[w+1]: {v[1..7], next[0]}; next = lane+1 within the
        // 8-lane row group (wrap).
        unsigned srcLane = (lane & 24u) | ((lane + 1u) & 7u);
#pragma unroll
        for (int k = 0; k < 4; k++) {
            f8 v = (k == 0) ? v0 : (k == 1) ? v1 : (k == 2) ? v2 : v3;
            float n = __shfl_sync(0xffffffffu, v.a.x, (int)srcLane);
            f8 r;
            r.a = make_float4(v.a.y, v.a.z, v.a.w, v.b.x);
            r.b = make_float4(v.b.y, v.b.z, v.b.w, n);
            stg256((k == 0) ? o0 : (k == 1) ? o1 : (k == 2) ? o2 : o3, r);
        }
    }
}

extern "C" void kernel_launch(void* const* d_in, const int* in_sizes, int n_in,
                              void* d_out, int out_size)
{
    const float* in  = (const float*)d_in[0];
    float*       out = (float*)d_out;
    swap_roll_kernel<<<QUARTER / THREADS, THREADS>>>(in, out);
}